// round 1
// baseline (speedup 1.0000x reference)
#include <cuda_runtime.h>
#include <cuda_bf16.h>
#include <cstdint>

// out[b] = V @ rho[b] @ V^T,  V = kron(uc[:,2:4], kron(ux, uy))  (256 x 128)
// Factored mode-by-mode: per batch
//   Phase A (columns of rho):  E1 (uy), E2 (ux) in-place in s_rho; N = uc-expand -> s_N (128x256)
//   Phase B (rows of N):       F1 (uy), F2 (ux) in-place in s_N;  final uc-expand -> gmem
//
// Row strides 129 / 257 floats keep all strided lane patterns conflict-free.

#define RS 129      // s_rho row stride (floats)
#define NS 257      // s_N   row stride (floats)

extern "C" __global__ void __launch_bounds__(256, 1)
qconv_kernel(const float* __restrict__ rho,
             const float* __restrict__ ux,
             const float* __restrict__ uy,
             const float* __restrict__ uc,
             float* __restrict__ out)
{
    extern __shared__ float smem[];
    float* s_rho = smem;                 // 128*129 floats
    float* s_N   = smem + 128 * RS;      // 128*257 floats
    __shared__ float s_ux[64], s_uy[64], s_uc[16];

    const int b = blockIdx.x;
    const int t = threadIdx.x;

    // ---- load small u matrices ----
    if (t < 64) { s_ux[t] = ux[t]; s_uy[t] = uy[t]; }
    else if (t < 80) { s_uc[t - 64] = uc[t - 64]; }

    // ---- load rho[b] (16384 floats) into s_rho with padded rows ----
    {
        const float4* g = (const float4*)(rho + (size_t)b * 16384);
        #pragma unroll
        for (int i = 0; i < 16; i++) {
            int e4 = t + i * 256;            // float4 index 0..4095
            float4 v = g[e4];
            int e = e4 * 4;
            int r = e >> 7;
            int c = e & 127;
            float* p = s_rho + r * RS + c;
            p[0] = v.x; p[1] = v.y; p[2] = v.z; p[3] = v.w;
        }
    }
    __syncthreads();

    // ---- E1: contract jy' with uy  (groups of 8 consecutive cols, in-place) ----
    {
        const int q  = t & 127;              // row
        const int g0 = (t >> 7) * 8;         // 8 of 16 groups per thread
        #pragma unroll
        for (int gi = 0; gi < 8; gi++) {
            float* p = s_rho + q * RS + (g0 + gi) * 8;
            float v[8];
            #pragma unroll
            for (int k = 0; k < 8; k++) v[k] = p[k];
            #pragma unroll
            for (int iy = 0; iy < 8; iy++) {
                float acc = 0.f;
                #pragma unroll
                for (int k = 0; k < 8; k++) acc = fmaf(s_uy[iy * 8 + k], v[k], acc);
                p[iy] = acc;
            }
        }
    }
    __syncthreads();

    // ---- E2: contract jx' with ux  (stride-8 groups within each 64-col block, in-place) ----
    {
        const int q  = t & 127;
        const int g0 = (t >> 7) * 8;
        #pragma unroll
        for (int gi = 0; gi < 8; gi++) {
            int u  = g0 + gi;                // 0..15
            int cp = u >> 3;                 // channel' 0/1
            int iy = u & 7;
            float* p = s_rho + q * RS + cp * 64 + iy;
            float v[8];
            #pragma unroll
            for (int k = 0; k < 8; k++) v[k] = p[k * 8];
            #pragma unroll
            for (int ix = 0; ix < 8; ix++) {
                float acc = 0.f;
                #pragma unroll
                for (int k = 0; k < 8; k++) acc = fmaf(s_ux[ix * 8 + k], v[k], acc);
                p[ix * 8] = acc;
            }
        }
    }
    __syncthreads();

    // ---- N: channel-expand columns 128 -> 256:  N[q, g*64+w] = uc[g,2]*E2[q,w] + uc[g,3]*E2[q,64+w]
    {
        const float c02 = s_uc[2],  c03 = s_uc[3];
        const float c12 = s_uc[6],  c13 = s_uc[7];
        const float c22 = s_uc[10], c23 = s_uc[11];
        const float c32 = s_uc[14], c33 = s_uc[15];
        #pragma unroll
        for (int i = 0; i < 32; i++) {
            int idx = t + i * 256;           // 0..8191  -> (q, w)
            int q = idx >> 6;
            int w = idx & 63;
            float a  = s_rho[q * RS + w];
            float bb = s_rho[q * RS + 64 + w];
            float* p = s_N + q * NS + w;
            p[0]   = fmaf(c02, a, c03 * bb);
            p[64]  = fmaf(c12, a, c13 * bb);
            p[128] = fmaf(c22, a, c23 * bb);
            p[192] = fmaf(c32, a, c33 * bb);
        }
    }
    __syncthreads();

    // ---- F1: contract ky with uy over row-groups of 8 consecutive rows (in-place, thread-per-column)
    {
        const int s = t;                     // column 0..255
        #pragma unroll
        for (int rg = 0; rg < 16; rg++) {
            float* p = s_N + rg * 8 * NS + s;
            float v[8];
            #pragma unroll
            for (int k = 0; k < 8; k++) v[k] = p[k * NS];
            #pragma unroll
            for (int iy = 0; iy < 8; iy++) {
                float acc = 0.f;
                #pragma unroll
                for (int k = 0; k < 8; k++) acc = fmaf(s_uy[iy * 8 + k], v[k], acc);
                p[iy * NS] = acc;
            }
        }
    }
    __syncthreads();

    // ---- F2: contract kx with ux over stride-8 row groups (in-place, thread-per-column)
    {
        const int s = t;
        #pragma unroll
        for (int u = 0; u < 16; u++) {
            int c  = u >> 3;
            int iy = u & 7;
            float* p = s_N + (c * 64 + iy) * NS + s;
            float v[8];
            #pragma unroll
            for (int k = 0; k < 8; k++) v[k] = p[k * 8 * NS];
            #pragma unroll
            for (int ix = 0; ix < 8; ix++) {
                float acc = 0.f;
                #pragma unroll
                for (int k = 0; k < 8; k++) acc = fmaf(s_ux[ix * 8 + k], v[k], acc);
                p[ix * 8 * NS] = acc;
            }
        }
    }
    __syncthreads();

    // ---- Final: channel-expand rows 128 -> 256, write to gmem (float4, coalesced)
    //      out[b, f*64+w, s] = uc[f,2]*F2[w, s] + uc[f,3]*F2[64+w, s]
    {
        const float ca[4] = { s_uc[2], s_uc[6], s_uc[10], s_uc[14] };
        const float cb[4] = { s_uc[3], s_uc[7], s_uc[11], s_uc[15] };
        float* ob = out + (size_t)b * 65536;
        #pragma unroll
        for (int i = 0; i < 16; i++) {
            int idx = t + i * 256;           // 0..4095 -> (w, s4)
            int w  = idx >> 6;
            int s  = (idx & 63) * 4;
            const float* pa = s_N + w * NS + s;
            const float* pb = s_N + (64 + w) * NS + s;
            float a0 = pa[0], a1 = pa[1], a2 = pa[2], a3 = pa[3];
            float b0 = pb[0], b1 = pb[1], b2 = pb[2], b3 = pb[3];
            #pragma unroll
            for (int f = 0; f < 4; f++) {
                float4 v;
                v.x = fmaf(ca[f], a0, cb[f] * b0);
                v.y = fmaf(ca[f], a1, cb[f] * b1);
                v.z = fmaf(ca[f], a2, cb[f] * b2);
                v.w = fmaf(ca[f], a3, cb[f] * b3);
                *(float4*)(ob + (size_t)(f * 64 + w) * 256 + s) = v;
            }
        }
    }
}

extern "C" void kernel_launch(void* const* d_in, const int* in_sizes, int n_in,
                              void* d_out, int out_size)
{
    const float* rho = (const float*)d_in[0];
    const float* ux  = (const float*)d_in[1];
    const float* uy  = (const float*)d_in[2];
    const float* uc  = (const float*)d_in[3];
    float* out = (float*)d_out;

    const int smem_bytes = (128 * RS + 128 * NS) * (int)sizeof(float);  // 197632
    cudaFuncSetAttribute(qconv_kernel,
                         cudaFuncAttributeMaxDynamicSharedMemorySize, smem_bytes);

    qconv_kernel<<<256, 256, smem_bytes>>>(rho, ux, uy, uc, out);
}

// round 3
// speedup vs baseline: 1.2766x; 1.2766x over previous
#include <cuda_runtime.h>
#include <cuda_bf16.h>
#include <cstdint>

// out[b] = V @ rho[b] @ V^T,  V = kron(uc[:,2:4], W),  W = kron(ux, uy) (64x64)
//
// Block form: rho = [[rho00, rho01],[rho10, rho11]] (64x64 blocks).
//   M_cd = W @ rho_cd @ W^T   (computed in place in one 128x128 smem buffer)
//   out(f,g)[i,j] = sum_{c,d} uc[f,c+2] * uc[g,d+2] * M_cd[i,j]   (fused into stores)
//
// Phase A: per-thread 64-value row segments, both 8x8 contractions in registers.
// Phase B: per-thread 64-value column segments, same.
// Row stride 129 floats keeps every lane pattern conflict-free.

#define RS 129

// In-place bilateral 8x8 transform on 64 values at p[k*STRIDE], k = kx*8+ky:
//   contract ky with uy (out iy), then kx with ux (out ix).
template<int STRIDE>
__device__ __forceinline__ void xform64(float* p, const float* s_uy, const float* s_ux)
{
    float z[64];
    #pragma unroll
    for (int k = 0; k < 64; k++) z[k] = p[k * STRIDE];

    // contract ky with uy
    #pragma unroll
    for (int kx = 0; kx < 8; kx++) {
        float t[8];
        #pragma unroll
        for (int iy = 0; iy < 8; iy++) {
            float acc = 0.f;
            #pragma unroll
            for (int k = 0; k < 8; k++) acc = fmaf(s_uy[iy * 8 + k], z[kx * 8 + k], acc);
            t[iy] = acc;
        }
        #pragma unroll
        for (int iy = 0; iy < 8; iy++) z[kx * 8 + iy] = t[iy];
    }
    // contract kx with ux
    #pragma unroll
    for (int iy = 0; iy < 8; iy++) {
        float t[8];
        #pragma unroll
        for (int ix = 0; ix < 8; ix++) {
            float acc = 0.f;
            #pragma unroll
            for (int k = 0; k < 8; k++) acc = fmaf(s_ux[ix * 8 + k], z[k * 8 + iy], acc);
            t[ix] = acc;
        }
        #pragma unroll
        for (int ix = 0; ix < 8; ix++) z[ix * 8 + iy] = t[ix];
    }

    #pragma unroll
    for (int k = 0; k < 64; k++) p[k * STRIDE] = z[k];
}

extern "C" __global__ void __launch_bounds__(256, 2)
qconv_kernel(const float* __restrict__ rho,
             const float* __restrict__ ux,
             const float* __restrict__ uy,
             const float* __restrict__ uc,
             float* __restrict__ out)
{
    extern __shared__ float s_m[];       // 128 * RS floats (66 KB)
    __shared__ float s_ux[64], s_uy[64], s_uc[16];

    const int b = blockIdx.x;
    const int t = threadIdx.x;

    if (t < 64)      { s_ux[t] = ux[t]; s_uy[t] = uy[t]; }
    else if (t < 80) { s_uc[t - 64] = uc[t - 64]; }

    // ---- load rho[b] (16384 floats) ----
    {
        const float4* g = (const float4*)(rho + (size_t)b * 16384);
        #pragma unroll
        for (int i = 0; i < 16; i++) {
            int e4 = t + i * 256;            // float4 index 0..4095
            float4 v = g[e4];
            int e = e4 * 4;
            int r = e >> 7;
            int c = e & 127;
            float* p = s_m + r * RS + c;
            p[0] = v.x; p[1] = v.y; p[2] = v.z; p[3] = v.w;
        }
    }
    __syncthreads();

    // ---- Phase A: column-side W^T. Thread owns (row r, channel block cb): 64 contiguous floats.
    {
        const int r  = t & 127;
        const int cb = t >> 7;
        xform64<1>(s_m + r * RS + cb * 64, s_uy, s_ux);
    }
    __syncthreads();

    // ---- Phase B: row-side W. Thread owns (col c, row-channel block rb): 64 floats stride RS.
    {
        const int c  = t & 127;
        const int rb = t >> 7;
        xform64<RS>(s_m + rb * 64 * RS + c, s_uy, s_ux);
    }
    __syncthreads();

    // ---- Epilogue: uc-expand 128x128 -> 256x256 fused into coalesced float4 stores.
    //      out[b, f*64+i, g*64+j] = sum_{c,d} uc[f,c+2] uc[g,d+2] M[c*64+i, d*64+j]
    {
        const float a0 = s_uc[2],  b0 = s_uc[3];
        const float a1 = s_uc[6],  b1 = s_uc[7];
        const float a2 = s_uc[10], b2 = s_uc[11];
        const float a3 = s_uc[14], b3 = s_uc[15];
        const float ga[4] = { a0, a1, a2, a3 };
        const float gb[4] = { b0, b1, b2, b3 };

        float* ob = out + (size_t)b * 65536;

        #pragma unroll
        for (int it = 0; it < 4; it++) {
            int pos = t + it * 256;          // 0..1023
            int i   = pos >> 4;              // 0..63
            int j   = (pos & 15) * 4;        // 0..60

            const float* p00 = s_m + i * RS + j;
            const float* p01 = p00 + 64;
            const float* p10 = p00 + 64 * RS;
            const float* p11 = p10 + 64;

            float m00[4], m01[4], m10[4], m11[4];
            #pragma unroll
            for (int e = 0; e < 4; e++) {
                m00[e] = p00[e]; m01[e] = p01[e];
                m10[e] = p10[e]; m11[e] = p11[e];
            }

            #pragma unroll
            for (int f = 0; f < 4; f++) {
                const float af = ga[f], bf = gb[f];
                float r0[4], r1[4];          // stage 1: contract row-channel c
                #pragma unroll
                for (int e = 0; e < 4; e++) {
                    r0[e] = fmaf(af, m00[e], bf * m10[e]);
                    r1[e] = fmaf(af, m01[e], bf * m11[e]);
                }
                float* orow = ob + (size_t)(f * 64 + i) * 256 + j;
                #pragma unroll
                for (int g = 0; g < 4; g++) { // stage 2: contract col-channel d
                    const float ag = ga[g], bg = gb[g];
                    float4 v;
                    v.x = fmaf(ag, r0[0], bg * r1[0]);
                    v.y = fmaf(ag, r0[1], bg * r1[1]);
                    v.z = fmaf(ag, r0[2], bg * r1[2]);
                    v.w = fmaf(ag, r0[3], bg * r1[3]);
                    *(float4*)(orow + g * 64) = v;
                }
            }
        }
    }
}

extern "C" void kernel_launch(void* const* d_in, const int* in_sizes, int n_in,
                              void* d_out, int out_size)
{
    const float* rho = (const float*)d_in[0];
    const float* ux  = (const float*)d_in[1];
    const float* uy  = (const float*)d_in[2];
    const float* uc  = (const float*)d_in[3];
    float* out = (float*)d_out;

    const int smem_bytes = 128 * RS * (int)sizeof(float);  // 66048
    cudaFuncSetAttribute(qconv_kernel,
                         cudaFuncAttributeMaxDynamicSharedMemorySize, smem_bytes);

    qconv_kernel<<<256, 256, smem_bytes>>>(rho, ux, uy, uc, out);
}